// round 13
// baseline (speedup 1.0000x reference)
#include <cuda_runtime.h>
#include <cuda_fp16.h>
#include <math_constants.h>
#include <cstdint>

#define NNODES 100000
#define EMAX   1600000
#define EPMAX  (EMAX + NNODES)
#define IN_F   256
#define HID_F  128
#define OUT_F  64
#define NB_    391          // ceil(NNODES/256)

// ---------------- scratch (static device globals; no allocation) ------------
__device__ __half g_h16[(size_t)NNODES * HID_F];    // GEMM output h (layer2 reuses)
__device__ __half g_out1h[(size_t)NNODES * HID_F];  // layer-1 output (fp16)
__device__ float g_as[NNODES], g_ad[NNODES];
__device__ int   g_deg[NNODES], g_cur[NNODES], g_incl[NNODES];
__device__ int   g_rowptr[NNODES + 1];
__device__ int   g_bsums[256];
__device__ int   g_ssrc[EPMAX];
__device__ __half g_w1[IN_F * HID_F];   // [N][K] fp16
__device__ __half g_w2[HID_F * OUT_F];  // [N][K] fp16

// ---------------- PTX helpers (sm_80-era ops only: valid on sm_103) ---------
__device__ __forceinline__ uint32_t smem_u32(const void* p) {
    uint32_t a;
    asm("{ .reg .u64 t; cvta.to.shared.u64 t, %1; cvt.u32.u64 %0, t; }" : "=r"(a) : "l"(p));
    return a;
}
__device__ __forceinline__ void ldsm4(uint32_t* r, uint32_t addr) {
    asm volatile("ldmatrix.sync.aligned.m8n8.x4.shared.b16 {%0,%1,%2,%3}, [%4];"
        : "=r"(r[0]), "=r"(r[1]), "=r"(r[2]), "=r"(r[3]) : "r"(addr));
}
__device__ __forceinline__ void mma16816(float* d, const uint32_t* a, const uint32_t* b) {
    asm volatile(
        "mma.sync.aligned.m16n8k16.row.col.f32.f16.f16.f32 "
        "{%0,%1,%2,%3}, {%4,%5,%6,%7}, {%8,%9}, {%0,%1,%2,%3};"
        : "+f"(d[0]), "+f"(d[1]), "+f"(d[2]), "+f"(d[3])
        : "r"(a[0]), "r"(a[1]), "r"(a[2]), "r"(a[3]), "r"(b[0]), "r"(b[1]));
}
__device__ __forceinline__ void cpasync16(uint32_t saddr, const void* g) {
    asm volatile("cp.async.cg.shared.global [%0], [%1], 16;" :: "r"(saddr), "l"(g));
}
#define CPASYNC_COMMIT() asm volatile("cp.async.commit_group;" ::: "memory")
#define CPASYNC_WAIT0()  asm volatile("cp.async.wait_group 0;" ::: "memory")
__device__ __forceinline__ float lrelu(float x) { return x > 0.0f ? x : 0.2f * x; }

// ---------------- k1: W fp16 transpose (deg zeroed by memset on s2) ---------
__global__ void conv_w(const float* __restrict__ W1, const float* __restrict__ W2) {
    int i = blockIdx.x * blockDim.x + threadIdx.x;
    if (i < IN_F * HID_F) {
        int k = i / HID_F, n = i % HID_F;
        g_w1[n * IN_F + k] = __float2half(W1[i]);
    } else if (i < IN_F * HID_F + HID_F * OUT_F) {
        int j = i - IN_F * HID_F;
        int k = j / OUT_F, n = j % OUT_F;
        g_w2[n * HID_F + k] = __float2half(W2[j]);
    }
}

// ---------------- k2: degree histogram ---------------------------------------
__global__ void count_deg(const int* __restrict__ dst, int E) {
    int i = blockIdx.x * blockDim.x + threadIdx.x;
    if (i < E) atomicAdd(&g_deg[dst[i]], 1);
}

// ---------------- k3: per-1024-block inclusive scan (coalesced) -------------
__global__ void scan1() {
    __shared__ int sh[1024];
    int i = blockIdx.x * 1024 + threadIdx.x;
    int v = (i < NNODES) ? g_deg[i] + 1 : 0;   // +1 self-loop
    sh[threadIdx.x] = v;
    __syncthreads();
    for (int off = 1; off < 1024; off <<= 1) {
        int t = (threadIdx.x >= off) ? sh[threadIdx.x - off] : 0;
        __syncthreads();
        sh[threadIdx.x] += t;
        __syncthreads();
    }
    if (i < NNODES) g_incl[i] = sh[threadIdx.x];
    if (threadIdx.x == 1023) g_bsums[blockIdx.x] = sh[1023];
}

// ---------------- k4: block-sum scan + rowptr/cursor + self-loop place ------
__global__ void scan23(int EP, int SB) {
    __shared__ int bs[128];
    int tid = threadIdx.x;
    if (tid < 128) bs[tid] = (tid < SB) ? g_bsums[tid] : 0;
    __syncthreads();
    for (int off = 1; off < 128; off <<= 1) {
        int v = (tid < 128 && tid >= off) ? bs[tid - off] : 0;
        __syncthreads();
        if (tid < 128) bs[tid] += v;
        __syncthreads();
    }
    int i = blockIdx.x * blockDim.x + tid;
    if (i < NNODES) {
        int b = i >> 10;
        int excl = bs[b] - g_bsums[b];           // exclusive prefix of block sums
        int rp = g_incl[i] - (g_deg[i] + 1) + excl;
        g_rowptr[i] = rp;
        g_ssrc[rp]  = i;                         // self-loop pre-placed first
        g_cur[i]    = rp + 1;                    // scatter cursor after self-loop
    }
    if (i == 0) g_rowptr[NNODES] = EP;
}

// ---------------- k5: scatter real edges into CSR ----------------------------
__global__ void scatter(const int* __restrict__ src, const int* __restrict__ dst, int E) {
    int i = blockIdx.x * blockDim.x + threadIdx.x;
    if (i >= E) return;
    int pos = atomicAdd(&g_cur[dst[i]], 1);
    g_ssrc[pos] = src[i];
}

// ---------------- fp16 mma.sync GEMM + fused alpha epilogue -----------------
template<int N_TILE, int K_TOT, typename AT>
__global__ void __launch_bounds__(256) gemm_mma(
    const AT* __restrict__ A, const __half* __restrict__ B,
    __half* __restrict__ Ch,
    const float* __restrict__ av_s, const float* __restrict__ av_d, int M)
{
    constexpr int WN    = N_TILE / 2;
    constexpr int NT    = WN / 8;
    constexpr int NCH   = K_TOT / 64;
    constexpr int RB    = K_TOT * 2;
    constexpr int BPART = N_TILE * K_TOT * 2;
    constexpr int BOFF  = 32768;
    constexpr int AVOFF = BOFF + BPART;
    extern __shared__ char smem[];
    const uint32_t sb = smem_u32(smem);
    const int tid = threadIdx.x;
    const int warp = tid >> 5, lane = tid & 31;
    const int wm = (warp >> 1) * 32;
    const int wn = (warp & 1) * WN;
    const int rowBase = blockIdx.x * 128;
    float* s_av = (float*)(smem + AVOFF);

    float  ldrf[4][8];
    uint4  ldrh[4];
    auto ldg_chunk = [&](int c) {
#pragma unroll
        for (int it = 0; it < 4; it++) {
            int idx = tid + it * 256;
            int r = idx >> 3, slot = idx & 7;
            int grow = rowBase + r;
            if constexpr (sizeof(AT) == 4) {
                if (grow < M) {
                    const float* p = (const float*)A + (size_t)grow * K_TOT + c * 64 + slot * 8;
                    *(float4*)&ldrf[it][0] = *(const float4*)p;
                    *(float4*)&ldrf[it][4] = *(const float4*)(p + 4);
                } else {
#pragma unroll
                    for (int j = 0; j < 8; j++) ldrf[it][j] = 0.f;
                }
            } else {
                if (grow < M)
                    ldrh[it] = *(const uint4*)((const __half*)A + (size_t)grow * K_TOT + c * 64 + slot * 8);
                else
                    ldrh[it] = make_uint4(0, 0, 0, 0);
            }
        }
    };
    auto sts_chunk = [&](int buf) {
#pragma unroll
        for (int it = 0; it < 4; it++) {
            int idx = tid + it * 256;
            int r = idx >> 3, slot = idx & 7;
            uint32_t so = (uint32_t)r * 128 + ((((uint32_t)slot) ^ (uint32_t)(r & 7)) << 4);
            if constexpr (sizeof(AT) == 4) {
                uint32_t h[4];
#pragma unroll
                for (int j = 0; j < 4; j++) {
                    __half2 hv = __float22half2_rn(make_float2(ldrf[it][2 * j], ldrf[it][2 * j + 1]));
                    h[j] = *(uint32_t*)&hv;
                }
                *(uint4*)(smem + buf * 16384 + so) = make_uint4(h[0], h[1], h[2], h[3]);
            } else {
                *(uint4*)(smem + buf * 16384 + so) = ldrh[it];
            }
        }
    };

    // prologue: A chunk-0 LDGs first (DRAM head start), then B via cp.async
    ldg_chunk(0);
    for (int idx = tid; idx < N_TILE * K_TOT / 8; idx += 256) {
        int n = idx / (K_TOT / 8), c8 = idx % (K_TOT / 8);
        uint32_t so = (uint32_t)n * RB + ((((uint32_t)c8) ^ (uint32_t)(n & 7)) << 4);
        cpasync16(sb + BOFF + so, B + (size_t)n * K_TOT + c8 * 8);
    }
    CPASYNC_COMMIT();
    for (int i = tid; i < N_TILE; i += 256) { s_av[i] = av_s[i]; s_av[N_TILE + i] = av_d[i]; }

    float acc[2][NT][4];
#pragma unroll
    for (int mt = 0; mt < 2; mt++)
#pragma unroll
        for (int nt = 0; nt < NT; nt++)
#pragma unroll
            for (int j = 0; j < 4; j++) acc[mt][nt][j] = 0.f;

    sts_chunk(0);
    CPASYNC_WAIT0();
    __syncthreads();

    for (int c = 0; c < NCH; c++) {
        if (c + 1 < NCH) ldg_chunk(c + 1);
        const uint32_t abase = sb + (c & 1) * 16384;
#pragma unroll
        for (int ks = 0; ks < 4; ks++) {
            uint32_t a[2][4];
#pragma unroll
            for (int mt = 0; mt < 2; mt++) {
                int row = wm + mt * 16 + (lane & 15);
                uint32_t kch = (uint32_t)(ks * 2 + (lane >> 4));
                ldsm4(a[mt], abase + (uint32_t)row * 128 + ((kch ^ (uint32_t)(row & 7)) << 4));
            }
            uint32_t b[NT][2];
#pragma unroll
            for (int p = 0; p < NT / 2; p++) {
                int n = wn + p * 16 + (lane & 7) + ((lane >> 4) << 3);
                uint32_t kch = (uint32_t)(c * 8 + ks * 2 + ((lane >> 3) & 1));
                uint32_t t[4];
                ldsm4(t, sb + BOFF + (uint32_t)n * RB + ((kch ^ (uint32_t)(n & 7)) << 4));
                b[2 * p][0] = t[0]; b[2 * p][1] = t[1];
                b[2 * p + 1][0] = t[2]; b[2 * p + 1][1] = t[3];
            }
#pragma unroll
            for (int mt = 0; mt < 2; mt++)
#pragma unroll
                for (int nt = 0; nt < NT; nt++)
                    mma16816(acc[mt][nt], a[mt], b[nt]);
        }
        if (c + 1 < NCH) sts_chunk((c + 1) & 1);
        __syncthreads();
    }

    // ---- epilogue: write fp16 C + fused alpha dots (fp32 accs) ----
    float* s_rs = (float*)smem;     // safe: last chunk read from buf 1 (NCH even)
    float* s_rd = s_rs + 128;
    if (tid < 128) { s_rs[tid] = 0.f; s_rd[tid] = 0.f; }
    __syncthreads();

#pragma unroll
    for (int mt = 0; mt < 2; mt++) {
        int lrow = wm + mt * 16 + (lane >> 2);
        int r0 = rowBase + lrow;
        float ps0 = 0.f, pd0 = 0.f, ps8 = 0.f, pd8 = 0.f;
#pragma unroll
        for (int nt = 0; nt < NT; nt++) {
            int cb = wn + nt * 8 + (lane & 3) * 2;
            float a0 = s_av[cb], a1 = s_av[cb + 1];
            float d0 = s_av[N_TILE + cb], d1 = s_av[N_TILE + cb + 1];
            ps0 += acc[mt][nt][0] * a0 + acc[mt][nt][1] * a1;
            pd0 += acc[mt][nt][0] * d0 + acc[mt][nt][1] * d1;
            ps8 += acc[mt][nt][2] * a0 + acc[mt][nt][3] * a1;
            pd8 += acc[mt][nt][2] * d0 + acc[mt][nt][3] * d1;
            if (r0 < M)
                *(__half2*)(Ch + (size_t)r0 * N_TILE + cb) =
                    __float22half2_rn(make_float2(acc[mt][nt][0], acc[mt][nt][1]));
            if (r0 + 8 < M)
                *(__half2*)(Ch + (size_t)(r0 + 8) * N_TILE + cb) =
                    __float22half2_rn(make_float2(acc[mt][nt][2], acc[mt][nt][3]));
        }
#pragma unroll
        for (int o = 1; o <= 2; o <<= 1) {
            ps0 += __shfl_xor_sync(0xffffffffu, ps0, o);
            pd0 += __shfl_xor_sync(0xffffffffu, pd0, o);
            ps8 += __shfl_xor_sync(0xffffffffu, ps8, o);
            pd8 += __shfl_xor_sync(0xffffffffu, pd8, o);
        }
        if ((lane & 3) == 0) {
            atomicAdd(&s_rs[lrow], ps0);
            atomicAdd(&s_rd[lrow], pd0);
            atomicAdd(&s_rs[lrow + 8], ps8);
            atomicAdd(&s_rd[lrow + 8], pd8);
        }
    }
    __syncthreads();
    if (tid < 128 && rowBase + tid < M) {
        g_as[rowBase + tid] = s_rs[tid];
        g_ad[rowBase + tid] = s_rd[tid];
    }
}

// ---------------- single-pass softmax aggregation (prefetch-pipelined) ------
template<int F, bool RELU, typename OUT_T>
__global__ void aggregate_fused(const __half* __restrict__ h,
                                const float* __restrict__ bias,
                                OUT_T* __restrict__ out) {
    constexpr int G = F / 8;
    int gidx = (blockIdx.x * blockDim.x + threadIdx.x) / G;
    int lane = threadIdx.x & (G - 1);
    if (gidx >= NNODES) return;
    unsigned wl = threadIdx.x & 31u;
    unsigned mask = ((1u << G) - 1u) << (wl & ~(unsigned)(G - 1));
    int beg = g_rowptr[gidx], end = g_rowptr[gidx + 1];
    float ad = g_ad[gidx];
    const __half* hl = h + (size_t)lane * 8;

    // prologue metadata load for chunk 0
    int s_pre = 0;
    float as_pre = 0.f;
    {
        int my = beg + lane;
        if (my < end) { s_pre = g_ssrc[my]; as_pre = g_as[s_pre]; }
    }

    float sm = 0.f;
    float acc[8] = {0.f, 0.f, 0.f, 0.f, 0.f, 0.f, 0.f, 0.f};
    for (int base = beg; base < end; base += G) {
        int s_my = s_pre;
        float as_my = as_pre;
        // prefetch next chunk's metadata (overlaps this chunk's row gathers)
        int nmy = base + G + lane;
        if (nmy < end) { s_pre = g_ssrc[nmy]; as_pre = g_as[s_pre]; }

        int cnt = min(G, end - base);
        int t = 0;
        for (; t + 8 <= cnt; t += 8) {
            float cc[8];
            uint4 hv[8];
#pragma unroll
            for (int q = 0; q < 8; q++) {
                int s = __shfl_sync(mask, s_my, t + q, G);
                float asv = __shfl_sync(mask, as_my, t + q, G);
                cc[q] = __expf(lrelu(asv + ad));
                hv[q] = *(const uint4*)(hl + (size_t)s * F);
            }
#pragma unroll
            for (int q = 0; q < 8; q++) {
                sm += cc[q];
                const __half2* hp = (const __half2*)&hv[q];
#pragma unroll
                for (int r = 0; r < 4; r++) {
                    float2 f = __half22float2(hp[r]);
                    acc[2 * r]     += cc[q] * f.x;
                    acc[2 * r + 1] += cc[q] * f.y;
                }
            }
        }
        for (; t < cnt; t++) {
            int s = __shfl_sync(mask, s_my, t, G);
            float asv = __shfl_sync(mask, as_my, t, G);
            float cc = __expf(lrelu(asv + ad));
            sm += cc;
            uint4 hv = *(const uint4*)(hl + (size_t)s * F);
            const __half2* hp = (const __half2*)&hv;
#pragma unroll
            for (int r = 0; r < 4; r++) {
                float2 f = __half22float2(hp[r]);
                acc[2 * r]     += cc * f.x;
                acc[2 * r + 1] += cc * f.y;
            }
        }
    }
    float inv = 1.0f / sm;
    float4 b0 = *(const float4*)(bias + lane * 8);
    float4 b1 = *(const float4*)(bias + lane * 8 + 4);
    float o[8];
    o[0] = acc[0] * inv + b0.x; o[1] = acc[1] * inv + b0.y;
    o[2] = acc[2] * inv + b0.z; o[3] = acc[3] * inv + b0.w;
    o[4] = acc[4] * inv + b1.x; o[5] = acc[5] * inv + b1.y;
    o[6] = acc[6] * inv + b1.z; o[7] = acc[7] * inv + b1.w;
    if (RELU) {
#pragma unroll
        for (int q = 0; q < 8; q++) o[q] = fmaxf(o[q], 0.f);
    }
    OUT_T* op = out + (size_t)gidx * F + lane * 8;
#pragma unroll
    for (int q = 0; q < 8; q++) op[q] = (OUT_T)o[q];
}

// ---------------- launch ----------------------------------------------------
extern "C" void kernel_launch(void* const* d_in, const int* in_sizes, int n_in,
                              void* d_out, int out_size) {
    const float* x   = (const float*)d_in[0];
    const int*   ei  = (const int*)d_in[1];
    const float* W1  = (const float*)d_in[2];
    const float* a1s = (const float*)d_in[3];
    const float* a1d = (const float*)d_in[4];
    const float* b1  = (const float*)d_in[5];
    const float* W2  = (const float*)d_in[6];
    const float* a2s = (const float*)d_in[7];
    const float* a2d = (const float*)d_in[8];
    const float* b2  = (const float*)d_in[9];
    float* out = (float*)d_out;

    int E  = in_sizes[1] / 2;
    int EP = E + NNODES;
    const int* src = ei;
    const int* dst = ei + E;

    __half *p_h16, *p_out1h, *p_w1, *p_w2;
    int *p_deg;
    cudaGetSymbolAddress((void**)&p_h16, g_h16);
    cudaGetSymbolAddress((void**)&p_out1h, g_out1h);
    cudaGetSymbolAddress((void**)&p_w1, g_w1);
    cudaGetSymbolAddress((void**)&p_w2, g_w2);
    cudaGetSymbolAddress((void**)&p_deg, g_deg);

    const int EB  = (E + 255) / 256;
    const int SB  = (NNODES + 1023) / 1024;   // 98 scan blocks
    const int GB  = (NNODES + 127) / 128;

    constexpr int SMEM1 = 32768 + HID_F * IN_F * 2 + HID_F * 8;   //  99328
    constexpr int SMEM2 = 32768 + OUT_F * HID_F * 2 + OUT_F * 8;  //  49664
    cudaFuncSetAttribute((void*)gemm_mma<HID_F, IN_F, float>,
                         cudaFuncAttributeMaxDynamicSharedMemorySize, SMEM1);
    cudaFuncSetAttribute((void*)gemm_mma<OUT_F, HID_F, __half>,
                         cudaFuncAttributeMaxDynamicSharedMemorySize, SMEM2);

    static cudaStream_t s2 = nullptr;
    static cudaEvent_t evFork = nullptr, evJoin = nullptr;
    if (s2 == nullptr) {
        cudaStreamCreateWithFlags(&s2, cudaStreamNonBlocking);
        cudaEventCreateWithFlags(&evFork, cudaEventDisableTiming);
        cudaEventCreateWithFlags(&evJoin, cudaEventDisableTiming);
    }

    // fork s2 at t=0; CSR chain starts immediately (deg zeroed by memset)
    cudaEventRecord(evFork, 0);
    cudaStreamWaitEvent(s2, evFork, 0);
    cudaMemsetAsync(p_deg, 0, NNODES * sizeof(int), s2);

    conv_w<<<160, 256>>>(W1, W2);                          // k1 (main)
    count_deg<<<EB, 256, 0, s2>>>(dst, E);                 // k2
    scan1<<<SB, 1024, 0, s2>>>();                          // k3

    gemm_mma<HID_F, IN_F, float><<<GB, 256, SMEM1>>>(      // k4 <- profiled
        x, p_w1, p_h16, a1s, a1d, NNODES);

    scan23<<<NB_, 256, 0, s2>>>(EP, SB);                   // k5
    scatter<<<EB, 256, 0, s2>>>(src, dst, E);              // k6
    cudaEventRecord(evJoin, s2);

    cudaStreamWaitEvent(0, evJoin, 0);
    aggregate_fused<HID_F, true, __half><<<NNODES * (HID_F / 8) / 256, 256>>>(
        p_h16, b1, p_out1h);                               // k7

    gemm_mma<OUT_F, HID_F, __half><<<GB, 256, SMEM2>>>(
        p_out1h, p_w2, p_h16, a2s, a2d, NNODES);           // k8

    aggregate_fused<OUT_F, false, float><<<NNODES * (OUT_F / 8) / 256, 256>>>(
        p_h16, b2, out);                                   // k9
}

// round 14
// speedup vs baseline: 1.1375x; 1.1375x over previous
#include <cuda_runtime.h>
#include <cuda_fp16.h>
#include <math_constants.h>
#include <cstdint>

#define NNODES 100000
#define EMAX   1600000
#define EPMAX  (EMAX + NNODES)
#define IN_F   256
#define HID_F  128
#define OUT_F  64
#define NB_    391          // ceil(NNODES/256)

// ---------------- scratch (static device globals; no allocation) ------------
__device__ __half g_h16[(size_t)NNODES * HID_F];    // GEMM output h (layer2 reuses)
__device__ __half g_out1h[(size_t)NNODES * HID_F];  // layer-1 output (fp16)
__device__ float g_as[NNODES], g_ad[NNODES];
__device__ int   g_deg[NNODES], g_cur[NNODES], g_incl[NNODES];
__device__ int   g_rowptr[NNODES + 1];
__device__ int   g_bsums[256];
__device__ int   g_ssrc[EPMAX];
__device__ __half g_w1[IN_F * HID_F];   // [N][K] fp16
__device__ __half g_w2[HID_F * OUT_F];  // [N][K] fp16

// ---------------- PTX helpers (sm_80-era ops only: valid on sm_103) ---------
__device__ __forceinline__ uint32_t smem_u32(const void* p) {
    uint32_t a;
    asm("{ .reg .u64 t; cvta.to.shared.u64 t, %1; cvt.u32.u64 %0, t; }" : "=r"(a) : "l"(p));
    return a;
}
__device__ __forceinline__ void ldsm4(uint32_t* r, uint32_t addr) {
    asm volatile("ldmatrix.sync.aligned.m8n8.x4.shared.b16 {%0,%1,%2,%3}, [%4];"
        : "=r"(r[0]), "=r"(r[1]), "=r"(r[2]), "=r"(r[3]) : "r"(addr));
}
__device__ __forceinline__ void mma16816(float* d, const uint32_t* a, const uint32_t* b) {
    asm volatile(
        "mma.sync.aligned.m16n8k16.row.col.f32.f16.f16.f32 "
        "{%0,%1,%2,%3}, {%4,%5,%6,%7}, {%8,%9}, {%0,%1,%2,%3};"
        : "+f"(d[0]), "+f"(d[1]), "+f"(d[2]), "+f"(d[3])
        : "r"(a[0]), "r"(a[1]), "r"(a[2]), "r"(a[3]), "r"(b[0]), "r"(b[1]));
}
__device__ __forceinline__ void cpasync16(uint32_t saddr, const void* g) {
    asm volatile("cp.async.cg.shared.global [%0], [%1], 16;" :: "r"(saddr), "l"(g));
}
#define CPASYNC_COMMIT() asm volatile("cp.async.commit_group;" ::: "memory")
#define CPASYNC_WAIT0()  asm volatile("cp.async.wait_group 0;" ::: "memory")
__device__ __forceinline__ float lrelu(float x) { return x > 0.0f ? x : 0.2f * x; }

// ---------------- k1: W fp16 transpose (deg zeroed by memset on s2) ---------
__global__ void conv_w(const float* __restrict__ W1, const float* __restrict__ W2) {
    int i = blockIdx.x * blockDim.x + threadIdx.x;
    if (i < IN_F * HID_F) {
        int k = i / HID_F, n = i % HID_F;
        g_w1[n * IN_F + k] = __float2half(W1[i]);
    } else if (i < IN_F * HID_F + HID_F * OUT_F) {
        int j = i - IN_F * HID_F;
        int k = j / OUT_F, n = j % OUT_F;
        g_w2[n * HID_F + k] = __float2half(W2[j]);
    }
}

// ---------------- k2: degree histogram ---------------------------------------
__global__ void count_deg(const int* __restrict__ dst, int E) {
    int i = blockIdx.x * blockDim.x + threadIdx.x;
    if (i < E) atomicAdd(&g_deg[dst[i]], 1);
}

// ---------------- k3: per-1024-block inclusive scan (coalesced) -------------
__global__ void scan1() {
    __shared__ int sh[1024];
    int i = blockIdx.x * 1024 + threadIdx.x;
    int v = (i < NNODES) ? g_deg[i] + 1 : 0;   // +1 self-loop
    sh[threadIdx.x] = v;
    __syncthreads();
    for (int off = 1; off < 1024; off <<= 1) {
        int t = (threadIdx.x >= off) ? sh[threadIdx.x - off] : 0;
        __syncthreads();
        sh[threadIdx.x] += t;
        __syncthreads();
    }
    if (i < NNODES) g_incl[i] = sh[threadIdx.x];
    if (threadIdx.x == 1023) g_bsums[blockIdx.x] = sh[1023];
}

// ---------------- k4: block-sum scan + rowptr/cursor + self-loop place ------
__global__ void scan23(int EP, int SB) {
    __shared__ int bs[128];
    int tid = threadIdx.x;
    if (tid < 128) bs[tid] = (tid < SB) ? g_bsums[tid] : 0;
    __syncthreads();
    for (int off = 1; off < 128; off <<= 1) {
        int v = (tid < 128 && tid >= off) ? bs[tid - off] : 0;
        __syncthreads();
        if (tid < 128) bs[tid] += v;
        __syncthreads();
    }
    int i = blockIdx.x * blockDim.x + tid;
    if (i < NNODES) {
        int b = i >> 10;
        int excl = bs[b] - g_bsums[b];           // exclusive prefix of block sums
        int rp = g_incl[i] - (g_deg[i] + 1) + excl;
        g_rowptr[i] = rp;
        g_ssrc[rp]  = i;                         // self-loop pre-placed first
        g_cur[i]    = rp + 1;                    // scatter cursor after self-loop
    }
    if (i == 0) g_rowptr[NNODES] = EP;
}

// ---------------- k5: scatter real edges into CSR ----------------------------
__global__ void scatter(const int* __restrict__ src, const int* __restrict__ dst, int E) {
    int i = blockIdx.x * blockDim.x + threadIdx.x;
    if (i >= E) return;
    int pos = atomicAdd(&g_cur[dst[i]], 1);
    g_ssrc[pos] = src[i];
}

// ---------------- fp16 mma.sync GEMM + fused alpha epilogue -----------------
template<int N_TILE, int K_TOT, typename AT>
__global__ void __launch_bounds__(256) gemm_mma(
    const AT* __restrict__ A, const __half* __restrict__ B,
    __half* __restrict__ Ch,
    const float* __restrict__ av_s, const float* __restrict__ av_d, int M)
{
    constexpr int WN    = N_TILE / 2;
    constexpr int NT    = WN / 8;
    constexpr int NCH   = K_TOT / 64;
    constexpr int RB    = K_TOT * 2;
    constexpr int BPART = N_TILE * K_TOT * 2;
    constexpr int BOFF  = 32768;
    constexpr int AVOFF = BOFF + BPART;
    extern __shared__ char smem[];
    const uint32_t sb = smem_u32(smem);
    const int tid = threadIdx.x;
    const int warp = tid >> 5, lane = tid & 31;
    const int wm = (warp >> 1) * 32;
    const int wn = (warp & 1) * WN;
    const int rowBase = blockIdx.x * 128;
    float* s_av = (float*)(smem + AVOFF);

    float  ldrf[4][8];
    uint4  ldrh[4];
    auto ldg_chunk = [&](int c) {
#pragma unroll
        for (int it = 0; it < 4; it++) {
            int idx = tid + it * 256;
            int r = idx >> 3, slot = idx & 7;
            int grow = rowBase + r;
            if constexpr (sizeof(AT) == 4) {
                if (grow < M) {
                    const float* p = (const float*)A + (size_t)grow * K_TOT + c * 64 + slot * 8;
                    *(float4*)&ldrf[it][0] = *(const float4*)p;
                    *(float4*)&ldrf[it][4] = *(const float4*)(p + 4);
                } else {
#pragma unroll
                    for (int j = 0; j < 8; j++) ldrf[it][j] = 0.f;
                }
            } else {
                if (grow < M)
                    ldrh[it] = *(const uint4*)((const __half*)A + (size_t)grow * K_TOT + c * 64 + slot * 8);
                else
                    ldrh[it] = make_uint4(0, 0, 0, 0);
            }
        }
    };
    auto sts_chunk = [&](int buf) {
#pragma unroll
        for (int it = 0; it < 4; it++) {
            int idx = tid + it * 256;
            int r = idx >> 3, slot = idx & 7;
            uint32_t so = (uint32_t)r * 128 + ((((uint32_t)slot) ^ (uint32_t)(r & 7)) << 4);
            if constexpr (sizeof(AT) == 4) {
                uint32_t h[4];
#pragma unroll
                for (int j = 0; j < 4; j++) {
                    __half2 hv = __float22half2_rn(make_float2(ldrf[it][2 * j], ldrf[it][2 * j + 1]));
                    h[j] = *(uint32_t*)&hv;
                }
                *(uint4*)(smem + buf * 16384 + so) = make_uint4(h[0], h[1], h[2], h[3]);
            } else {
                *(uint4*)(smem + buf * 16384 + so) = ldrh[it];
            }
        }
    };

    // prologue: A chunk-0 LDGs first (DRAM head start), then B via cp.async
    ldg_chunk(0);
    for (int idx = tid; idx < N_TILE * K_TOT / 8; idx += 256) {
        int n = idx / (K_TOT / 8), c8 = idx % (K_TOT / 8);
        uint32_t so = (uint32_t)n * RB + ((((uint32_t)c8) ^ (uint32_t)(n & 7)) << 4);
        cpasync16(sb + BOFF + so, B + (size_t)n * K_TOT + c8 * 8);
    }
    CPASYNC_COMMIT();
    for (int i = tid; i < N_TILE; i += 256) { s_av[i] = av_s[i]; s_av[N_TILE + i] = av_d[i]; }

    float acc[2][NT][4];
#pragma unroll
    for (int mt = 0; mt < 2; mt++)
#pragma unroll
        for (int nt = 0; nt < NT; nt++)
#pragma unroll
            for (int j = 0; j < 4; j++) acc[mt][nt][j] = 0.f;

    sts_chunk(0);
    CPASYNC_WAIT0();
    __syncthreads();

    for (int c = 0; c < NCH; c++) {
        if (c + 1 < NCH) ldg_chunk(c + 1);
        const uint32_t abase = sb + (c & 1) * 16384;
#pragma unroll
        for (int ks = 0; ks < 4; ks++) {
            uint32_t a[2][4];
#pragma unroll
            for (int mt = 0; mt < 2; mt++) {
                int row = wm + mt * 16 + (lane & 15);
                uint32_t kch = (uint32_t)(ks * 2 + (lane >> 4));
                ldsm4(a[mt], abase + (uint32_t)row * 128 + ((kch ^ (uint32_t)(row & 7)) << 4));
            }
            uint32_t b[NT][2];
#pragma unroll
            for (int p = 0; p < NT / 2; p++) {
                int n = wn + p * 16 + (lane & 7) + ((lane >> 4) << 3);
                uint32_t kch = (uint32_t)(c * 8 + ks * 2 + ((lane >> 3) & 1));
                uint32_t t[4];
                ldsm4(t, sb + BOFF + (uint32_t)n * RB + ((kch ^ (uint32_t)(n & 7)) << 4));
                b[2 * p][0] = t[0]; b[2 * p][1] = t[1];
                b[2 * p + 1][0] = t[2]; b[2 * p + 1][1] = t[3];
            }
#pragma unroll
            for (int mt = 0; mt < 2; mt++)
#pragma unroll
                for (int nt = 0; nt < NT; nt++)
                    mma16816(acc[mt][nt], a[mt], b[nt]);
        }
        if (c + 1 < NCH) sts_chunk((c + 1) & 1);
        __syncthreads();
    }

    // ---- epilogue: write fp16 C + fused alpha dots (fp32 accs) ----
    float* s_rs = (float*)smem;     // safe: last chunk read from buf 1 (NCH even)
    float* s_rd = s_rs + 128;
    if (tid < 128) { s_rs[tid] = 0.f; s_rd[tid] = 0.f; }
    __syncthreads();

#pragma unroll
    for (int mt = 0; mt < 2; mt++) {
        int lrow = wm + mt * 16 + (lane >> 2);
        int r0 = rowBase + lrow;
        float ps0 = 0.f, pd0 = 0.f, ps8 = 0.f, pd8 = 0.f;
#pragma unroll
        for (int nt = 0; nt < NT; nt++) {
            int cb = wn + nt * 8 + (lane & 3) * 2;
            float a0 = s_av[cb], a1 = s_av[cb + 1];
            float d0 = s_av[N_TILE + cb], d1 = s_av[N_TILE + cb + 1];
            ps0 += acc[mt][nt][0] * a0 + acc[mt][nt][1] * a1;
            pd0 += acc[mt][nt][0] * d0 + acc[mt][nt][1] * d1;
            ps8 += acc[mt][nt][2] * a0 + acc[mt][nt][3] * a1;
            pd8 += acc[mt][nt][2] * d0 + acc[mt][nt][3] * d1;
            if (r0 < M)
                *(__half2*)(Ch + (size_t)r0 * N_TILE + cb) =
                    __float22half2_rn(make_float2(acc[mt][nt][0], acc[mt][nt][1]));
            if (r0 + 8 < M)
                *(__half2*)(Ch + (size_t)(r0 + 8) * N_TILE + cb) =
                    __float22half2_rn(make_float2(acc[mt][nt][2], acc[mt][nt][3]));
        }
#pragma unroll
        for (int o = 1; o <= 2; o <<= 1) {
            ps0 += __shfl_xor_sync(0xffffffffu, ps0, o);
            pd0 += __shfl_xor_sync(0xffffffffu, pd0, o);
            ps8 += __shfl_xor_sync(0xffffffffu, ps8, o);
            pd8 += __shfl_xor_sync(0xffffffffu, pd8, o);
        }
        if ((lane & 3) == 0) {
            atomicAdd(&s_rs[lrow], ps0);
            atomicAdd(&s_rd[lrow], pd0);
            atomicAdd(&s_rs[lrow + 8], ps8);
            atomicAdd(&s_rd[lrow + 8], pd8);
        }
    }
    __syncthreads();
    if (tid < 128 && rowBase + tid < M) {
        g_as[rowBase + tid] = s_rs[tid];
        g_ad[rowBase + tid] = s_rd[tid];
    }
}

// ---------------- single-pass softmax aggregation ----------------------------
// Batch-4 edges: products accumulated with HFMA2 (fp16), batch subtotal flushed
// to fp32 accumulators. Remainder edges use the exact fp32 path.
template<int F, bool RELU, typename OUT_T>
__global__ void __launch_bounds__(256) aggregate_fused(
    const __half* __restrict__ h,
    const float* __restrict__ bias,
    OUT_T* __restrict__ out)
{
    constexpr int G = F / 8;
    int gidx = (blockIdx.x * blockDim.x + threadIdx.x) / G;
    int lane = threadIdx.x & (G - 1);
    if (gidx >= NNODES) return;
    unsigned wl = threadIdx.x & 31u;
    unsigned mask = ((1u << G) - 1u) << (wl & ~(unsigned)(G - 1));
    int beg = g_rowptr[gidx], end = g_rowptr[gidx + 1];
    float ad = g_ad[gidx];
    const __half* hl = h + (size_t)lane * 8;

    // prologue metadata load for chunk 0
    int s_pre = 0;
    float as_pre = 0.f;
    {
        int my = beg + lane;
        if (my < end) { s_pre = g_ssrc[my]; as_pre = g_as[s_pre]; }
    }

    float sm = 0.f;
    float accf[8] = {0.f, 0.f, 0.f, 0.f, 0.f, 0.f, 0.f, 0.f};
    for (int base = beg; base < end; base += G) {
        int s_my = s_pre;
        float as_my = as_pre;
        int nmy = base + G + lane;
        if (nmy < end) { s_pre = g_ssrc[nmy]; as_pre = g_as[s_pre]; }

        int cnt = min(G, end - base);
        int t = 0;
        for (; t + 4 <= cnt; t += 4) {
            float cc[4];
            uint4 hv[4];
#pragma unroll
            for (int q = 0; q < 4; q++) {
                int s = __shfl_sync(mask, s_my, t + q, G);
                float asv = __shfl_sync(mask, as_my, t + q, G);
                cc[q] = __expf(lrelu(asv + ad));
                hv[q] = *(const uint4*)(hl + (size_t)s * F);
            }
            __half2 acch[4];
            __half2 hz = __float2half2_rn(0.f);
#pragma unroll
            for (int r = 0; r < 4; r++) acch[r] = hz;
#pragma unroll
            for (int q = 0; q < 4; q++) {
                sm += cc[q];
                __half2 cch = __float2half2_rn(cc[q]);
                const __half2* hp = (const __half2*)&hv[q];
#pragma unroll
                for (int r = 0; r < 4; r++)
                    acch[r] = __hfma2(cch, hp[r], acch[r]);
            }
#pragma unroll
            for (int r = 0; r < 4; r++) {
                float2 f = __half22float2(acch[r]);
                accf[2 * r]     += f.x;
                accf[2 * r + 1] += f.y;
            }
        }
        for (; t < cnt; t++) {
            int s = __shfl_sync(mask, s_my, t, G);
            float asv = __shfl_sync(mask, as_my, t, G);
            float cc = __expf(lrelu(asv + ad));
            sm += cc;
            uint4 hv = *(const uint4*)(hl + (size_t)s * F);
            const __half2* hp = (const __half2*)&hv;
#pragma unroll
            for (int r = 0; r < 4; r++) {
                float2 f = __half22float2(hp[r]);
                accf[2 * r]     += cc * f.x;
                accf[2 * r + 1] += cc * f.y;
            }
        }
    }
    float inv = 1.0f / sm;
    float4 b0 = *(const float4*)(bias + lane * 8);
    float4 b1 = *(const float4*)(bias + lane * 8 + 4);
    float o[8];
    o[0] = accf[0] * inv + b0.x; o[1] = accf[1] * inv + b0.y;
    o[2] = accf[2] * inv + b0.z; o[3] = accf[3] * inv + b0.w;
    o[4] = accf[4] * inv + b1.x; o[5] = accf[5] * inv + b1.y;
    o[6] = accf[6] * inv + b1.z; o[7] = accf[7] * inv + b1.w;
    if (RELU) {
#pragma unroll
        for (int q = 0; q < 8; q++) o[q] = fmaxf(o[q], 0.f);
    }
    OUT_T* op = out + (size_t)gidx * F + lane * 8;
#pragma unroll
    for (int q = 0; q < 8; q++) op[q] = (OUT_T)o[q];
}

// ---------------- launch ----------------------------------------------------
extern "C" void kernel_launch(void* const* d_in, const int* in_sizes, int n_in,
                              void* d_out, int out_size) {
    const float* x   = (const float*)d_in[0];
    const int*   ei  = (const int*)d_in[1];
    const float* W1  = (const float*)d_in[2];
    const float* a1s = (const float*)d_in[3];
    const float* a1d = (const float*)d_in[4];
    const float* b1  = (const float*)d_in[5];
    const float* W2  = (const float*)d_in[6];
    const float* a2s = (const float*)d_in[7];
    const float* a2d = (const float*)d_in[8];
    const float* b2  = (const float*)d_in[9];
    float* out = (float*)d_out;

    int E  = in_sizes[1] / 2;
    int EP = E + NNODES;
    const int* src = ei;
    const int* dst = ei + E;

    __half *p_h16, *p_out1h, *p_w1, *p_w2;
    int *p_deg;
    cudaGetSymbolAddress((void**)&p_h16, g_h16);
    cudaGetSymbolAddress((void**)&p_out1h, g_out1h);
    cudaGetSymbolAddress((void**)&p_w1, g_w1);
    cudaGetSymbolAddress((void**)&p_w2, g_w2);
    cudaGetSymbolAddress((void**)&p_deg, g_deg);

    const int EB  = (E + 255) / 256;
    const int SB  = (NNODES + 1023) / 1024;   // 98 scan blocks
    const int GB  = (NNODES + 127) / 128;

    constexpr int SMEM1 = 32768 + HID_F * IN_F * 2 + HID_F * 8;   //  99328
    constexpr int SMEM2 = 32768 + OUT_F * HID_F * 2 + OUT_F * 8;  //  49664
    cudaFuncSetAttribute((void*)gemm_mma<HID_F, IN_F, float>,
                         cudaFuncAttributeMaxDynamicSharedMemorySize, SMEM1);
    cudaFuncSetAttribute((void*)gemm_mma<OUT_F, HID_F, __half>,
                         cudaFuncAttributeMaxDynamicSharedMemorySize, SMEM2);

    static cudaStream_t s2 = nullptr;
    static cudaEvent_t evFork = nullptr, evJoin = nullptr;
    if (s2 == nullptr) {
        cudaStreamCreateWithFlags(&s2, cudaStreamNonBlocking);
        cudaEventCreateWithFlags(&evFork, cudaEventDisableTiming);
        cudaEventCreateWithFlags(&evJoin, cudaEventDisableTiming);
    }

    // fork s2 at t=0; CSR chain starts immediately (deg zeroed by memset)
    cudaEventRecord(evFork, 0);
    cudaStreamWaitEvent(s2, evFork, 0);
    cudaMemsetAsync(p_deg, 0, NNODES * sizeof(int), s2);

    conv_w<<<160, 256>>>(W1, W2);                          // k1 (main)
    count_deg<<<EB, 256, 0, s2>>>(dst, E);                 // k2
    scan1<<<SB, 1024, 0, s2>>>();                          // k3

    gemm_mma<HID_F, IN_F, float><<<GB, 256, SMEM1>>>(      // k4 <- profiled
        x, p_w1, p_h16, a1s, a1d, NNODES);

    scan23<<<NB_, 256, 0, s2>>>(EP, SB);                   // k5
    scatter<<<EB, 256, 0, s2>>>(src, dst, E);              // k6
    cudaEventRecord(evJoin, s2);

    cudaStreamWaitEvent(0, evJoin, 0);
    aggregate_fused<HID_F, true, __half><<<NNODES * (HID_F / 8) / 256, 256>>>(
        p_h16, b1, p_out1h);                               // k7

    gemm_mma<OUT_F, HID_F, __half><<<GB, 256, SMEM2>>>(
        p_out1h, p_w2, p_h16, a2s, a2d, NNODES);           // k8

    aggregate_fused<OUT_F, false, float><<<NNODES * (OUT_F / 8) / 256, 256>>>(
        p_h16, b2, out);                                   // k9
}